// round 2
// baseline (speedup 1.0000x reference)
#include <cuda_runtime.h>

#define N_NODES 50000
#define N_EDGES 800000
#define DIM 128
#define NEG_SLOPE 0.01f

// -------- scratch (allocation-free rule: __device__ globals) --------
__device__ float g_deg[N_NODES];
__device__ float g_hsum[(size_t)N_NODES * DIM];
__device__ float g_ha_src[(size_t)N_NODES * DIM];
__device__ float g_ha_dst[(size_t)N_NODES * DIM];
__device__ float g_s[N_EDGES];
__device__ float g_denom[N_NODES];

// -------- zero everything that gets accumulated --------
__global__ void zero_kernel(float* __restrict__ out) {
    int i = blockIdx.x * blockDim.x + threadIdx.x;
    int stride = gridDim.x * blockDim.x;
    for (int j = i; j < N_NODES * DIM; j += stride) {
        g_hsum[j] = 0.0f;
        out[j] = 0.0f;
    }
    for (int j = i; j < N_NODES; j += stride) {
        g_deg[j] = 0.0f;
        g_denom[j] = 0.0f;
    }
}

// -------- phase 1: deg + sum of x[src] onto dst (one warp per edge) --------
__global__ void scatter_mean_kernel(const float* __restrict__ x,
                                    const int* __restrict__ src,
                                    const int* __restrict__ dst) {
    int e = blockIdx.x * 8 + (threadIdx.x >> 5);
    int lane = threadIdx.x & 31;
    if (e >= N_EDGES) return;
    int s = src[e];
    int d = dst[e];
    float4 v = *(const float4*)(x + (size_t)s * DIM + lane * 4);
    float* o = g_hsum + (size_t)d * DIM + lane * 4;
    atomicAdd(o + 0, v.x);
    atomicAdd(o + 1, v.y);
    atomicAdd(o + 2, v.z);
    atomicAdd(o + 3, v.w);
    if (lane == 0) atomicAdd(&g_deg[d], 1.0f);
}

// -------- GEMM: C[M,128] = scale(A)[M,128] @ W[128,128] + bias --------
// block = 256 threads; tile 64 rows x 128 cols; 4x8 register micro-tile.
// if deg != nullptr, A rows are scaled by 1/max(deg[row],1) on load (mean).
__global__ __launch_bounds__(256) void gemm_kernel(const float* __restrict__ A,
                                                   const float* __restrict__ W,
                                                   const float* __restrict__ bias,
                                                   const float* __restrict__ deg,
                                                   float* __restrict__ C) {
    __shared__ float W_s[32][128];
    __shared__ float A_s[32][64];   // [k][row], f4-aligned rows

    int t = threadIdx.x;
    int tx = t & 15;       // 16 col-groups of 8
    int ty = t >> 4;       // 16 row-groups of 4
    int row0 = blockIdx.x * 64;

    float acc[4][8];
#pragma unroll
    for (int i = 0; i < 4; i++)
#pragma unroll
        for (int j = 0; j < 8; j++) acc[i][j] = 0.0f;

    for (int k0 = 0; k0 < 128; k0 += 32) {
        // load W chunk: 32x128 floats = 1024 float4
#pragma unroll
        for (int i = 0; i < 4; i++) {
            int f = i * 256 + t;
            int kk = f >> 5;
            int nq = f & 31;
            *(float4*)&W_s[kk][nq * 4] =
                *(const float4*)(W + (size_t)(k0 + kk) * 128 + nq * 4);
        }
        // load A chunk transposed: 64 rows x 32 k = 512 float4
#pragma unroll
        for (int i = 0; i < 2; i++) {
            int f = i * 256 + t;
            int row = f >> 3;       // 8 float4 per row-chunk
            int kq = f & 7;
            int grow = row0 + row;
            float4 v = make_float4(0.f, 0.f, 0.f, 0.f);
            if (grow < N_NODES) {
                v = *(const float4*)(A + (size_t)grow * 128 + k0 + kq * 4);
                if (deg != nullptr) {
                    float sc = 1.0f / fmaxf(deg[grow], 1.0f);
                    v.x *= sc; v.y *= sc; v.z *= sc; v.w *= sc;
                }
            }
            A_s[kq * 4 + 0][row] = v.x;
            A_s[kq * 4 + 1][row] = v.y;
            A_s[kq * 4 + 2][row] = v.z;
            A_s[kq * 4 + 3][row] = v.w;
        }
        __syncthreads();

#pragma unroll
        for (int kk = 0; kk < 32; kk++) {
            float4 a  = *(float4*)&A_s[kk][ty * 4];
            float4 w0 = *(float4*)&W_s[kk][tx * 8];
            float4 w1 = *(float4*)&W_s[kk][tx * 8 + 4];
            float av[4] = {a.x, a.y, a.z, a.w};
            float wv[8] = {w0.x, w0.y, w0.z, w0.w, w1.x, w1.y, w1.z, w1.w};
#pragma unroll
            for (int i = 0; i < 4; i++)
#pragma unroll
                for (int j = 0; j < 8; j++) acc[i][j] = fmaf(av[i], wv[j], acc[i][j]);
        }
        __syncthreads();
    }

    float4 b0 = *(const float4*)(bias + tx * 8);
    float4 b1 = *(const float4*)(bias + tx * 8 + 4);
#pragma unroll
    for (int i = 0; i < 4; i++) {
        int grow = row0 + ty * 4 + i;
        if (grow < N_NODES) {
            float4 o0 = make_float4(acc[i][0] + b0.x, acc[i][1] + b0.y,
                                    acc[i][2] + b0.z, acc[i][3] + b0.w);
            float4 o1 = make_float4(acc[i][4] + b1.x, acc[i][5] + b1.y,
                                    acc[i][6] + b1.z, acc[i][7] + b1.w);
            *(float4*)(C + (size_t)grow * 128 + tx * 8) = o0;
            *(float4*)(C + (size_t)grow * 128 + tx * 8 + 4) = o1;
        }
    }
}

__device__ __forceinline__ float leaky(float v) {
    return v > 0.0f ? v : NEG_SLOPE * v;
}

// -------- phase 3: edge scores s = exp(att(leaky(ha_src[s]+ha_dst[d]))) --------
__global__ void edge_score_kernel(const int* __restrict__ src,
                                  const int* __restrict__ dst,
                                  const float* __restrict__ att_w,
                                  const float* __restrict__ att_b) {
    int e = blockIdx.x * 8 + (threadIdx.x >> 5);
    int lane = threadIdx.x & 31;
    if (e >= N_EDGES) return;
    int s = src[e];
    int d = dst[e];
    float4 a = *(const float4*)(g_ha_src + (size_t)s * DIM + lane * 4);
    float4 b = *(const float4*)(g_ha_dst + (size_t)d * DIM + lane * 4);
    float4 w = *(const float4*)(att_w + lane * 4);
    float p = leaky(a.x + b.x) * w.x + leaky(a.y + b.y) * w.y +
              leaky(a.z + b.z) * w.z + leaky(a.w + b.w) * w.w;
#pragma unroll
    for (int o = 16; o > 0; o >>= 1) p += __shfl_xor_sync(0xFFFFFFFFu, p, o);
    if (lane == 0) {
        float sc = __expf(p + att_b[0]);
        g_s[e] = sc;
        atomicAdd(&g_denom[d], sc);
    }
}

// -------- phase 4: out[dst] += x[src] * (s / denom[dst]) --------
__global__ void edge_agg_kernel(const float* __restrict__ x,
                                const int* __restrict__ src,
                                const int* __restrict__ dst,
                                float* __restrict__ out) {
    int e = blockIdx.x * 8 + (threadIdx.x >> 5);
    int lane = threadIdx.x & 31;
    if (e >= N_EDGES) return;
    int s = src[e];
    int d = dst[e];
    float a = g_s[e] / g_denom[d];
    float4 v = *(const float4*)(x + (size_t)s * DIM + lane * 4);
    float* o = out + (size_t)d * DIM + lane * 4;
    atomicAdd(o + 0, v.x * a);
    atomicAdd(o + 1, v.y * a);
    atomicAdd(o + 2, v.z * a);
    atomicAdd(o + 3, v.w * a);
}

extern "C" void kernel_launch(void* const* d_in, const int* in_sizes, int n_in,
                              void* d_out, int out_size) {
    const float* x     = (const float*)d_in[0];
    const int*   src   = (const int*)d_in[1];
    const int*   dst   = (const int*)d_in[2];
    const float* src_w = (const float*)d_in[3];
    const float* src_b = (const float*)d_in[4];
    const float* dst_w = (const float*)d_in[5];
    const float* dst_b = (const float*)d_in[6];
    const float* att_w = (const float*)d_in[7];
    const float* att_b = (const float*)d_in[8];
    float* out = (float*)d_out;

    float *p_hsum, *p_deg, *p_ha_src, *p_ha_dst;
    cudaGetSymbolAddress((void**)&p_hsum,   g_hsum);
    cudaGetSymbolAddress((void**)&p_deg,    g_deg);
    cudaGetSymbolAddress((void**)&p_ha_src, g_ha_src);
    cudaGetSymbolAddress((void**)&p_ha_dst, g_ha_dst);

    const int EDGE_BLOCKS = (N_EDGES + 7) / 8;      // 8 warps per 256-thread block
    const int GEMM_BLOCKS = (N_NODES + 63) / 64;

    zero_kernel<<<2048, 256>>>(out);
    scatter_mean_kernel<<<EDGE_BLOCKS, 256>>>(x, src, dst);
    gemm_kernel<<<GEMM_BLOCKS, 256>>>(x,      src_w, src_b, nullptr, p_ha_src);
    gemm_kernel<<<GEMM_BLOCKS, 256>>>(p_hsum, dst_w, dst_b, p_deg,   p_ha_dst);
    edge_score_kernel<<<EDGE_BLOCKS, 256>>>(src, dst, att_w, att_b);
    edge_agg_kernel<<<EDGE_BLOCKS, 256>>>(x, src, dst, out);
}

// round 4
// speedup vs baseline: 2.2474x; 2.2474x over previous
#include <cuda_runtime.h>

#define N_NODES 50000
#define N_EDGES 800000
#define DIM 128
#define NEG_SLOPE 0.01f

// -------- scratch (allocation-free rule: __device__ globals) --------
__device__ int   g_count[N_NODES];          // degree counts / fill cursors
__device__ int   g_row_ptr[N_NODES + 1];    // CSR row pointers (by dst)
__device__ int   g_csr_src[N_EDGES];        // src index per CSR slot
__device__ float g_hmean[(size_t)N_NODES * DIM];
__device__ float g_ha_src[(size_t)N_NODES * DIM];
__device__ float g_ha_dst[(size_t)N_NODES * DIM];

// ================= CSR build =================

__global__ void zero_count_kernel() {
    int i = blockIdx.x * blockDim.x + threadIdx.x;
    if (i < N_NODES) g_count[i] = 0;
}

__global__ void count_kernel(const int* __restrict__ dst) {
    int e = blockIdx.x * blockDim.x + threadIdx.x;
    if (e < N_EDGES) atomicAdd(&g_count[dst[e]], 1);
}

// single-block exclusive scan of g_count -> g_row_ptr; resets g_count to 0.
__global__ __launch_bounds__(1024) void scan_kernel() {
    __shared__ int warp_sums[32];
    __shared__ int s_carry;
    int tid = threadIdx.x, lane = tid & 31, wid = tid >> 5;
    if (tid == 0) s_carry = 0;
    __syncthreads();

    for (int base = 0; base < N_NODES; base += 4096) {
        int idx0 = base + tid * 4;
        int v[4];
        int tot = 0;
#pragma unroll
        for (int k = 0; k < 4; k++) {
            int i = idx0 + k;
            v[k] = (i < N_NODES) ? g_count[i] : 0;
            if (i < N_NODES) g_count[i] = 0;   // reset for cursor reuse
            tot += v[k];
        }
        // warp inclusive scan of per-thread totals
        int incl = tot;
#pragma unroll
        for (int o = 1; o < 32; o <<= 1) {
            int t = __shfl_up_sync(0xFFFFFFFFu, incl, o);
            if (lane >= o) incl += t;
        }
        if (lane == 31) warp_sums[wid] = incl;
        __syncthreads();
        if (wid == 0) {
            int ws = warp_sums[lane];
            int wincl = ws;
#pragma unroll
            for (int o = 1; o < 32; o <<= 1) {
                int t = __shfl_up_sync(0xFFFFFFFFu, wincl, o);
                if (lane >= o) wincl += t;
            }
            warp_sums[lane] = wincl - ws;      // exclusive warp offsets
        }
        __syncthreads();
        int run = (incl - tot) + warp_sums[wid] + s_carry;
#pragma unroll
        for (int k = 0; k < 4; k++) {
            int i = idx0 + k;
            if (i < N_NODES) g_row_ptr[i] = run;
            run += v[k];
        }
        __syncthreads();
        if (tid == 1023) s_carry = run;        // carry + full chunk total
        __syncthreads();
    }
    if (threadIdx.x == 0) g_row_ptr[N_NODES] = s_carry;
}

__global__ void fill_kernel(const int* __restrict__ src,
                            const int* __restrict__ dst) {
    int e = blockIdx.x * blockDim.x + threadIdx.x;
    if (e < N_EDGES) {
        int d = dst[e];
        int pos = g_row_ptr[d] + atomicAdd(&g_count[d], 1);
        g_csr_src[pos] = src[e];
    }
}

// ================= phase 1: mean aggregation (warp per node, gather) =========

__global__ __launch_bounds__(256) void mean_kernel(const float* __restrict__ x) {
    int node = blockIdx.x * 8 + (threadIdx.x >> 5);
    if (node >= N_NODES) return;
    int lane = threadIdx.x & 31;
    int beg = g_row_ptr[node];
    int end = g_row_ptr[node + 1];

    float4 acc = make_float4(0.f, 0.f, 0.f, 0.f);
    for (int base = beg; base < end; base += 32) {
        int cnt = min(32, end - base);
        int s = (lane < cnt) ? g_csr_src[base + lane] : 0;
#pragma unroll 4
        for (int j = 0; j < cnt; j++) {
            int sj = __shfl_sync(0xFFFFFFFFu, s, j);
            float4 v = *(const float4*)(x + (size_t)sj * DIM + lane * 4);
            acc.x += v.x; acc.y += v.y; acc.z += v.z; acc.w += v.w;
        }
    }
    float inv = 1.0f / fmaxf((float)(end - beg), 1.0f);
    acc.x *= inv; acc.y *= inv; acc.z *= inv; acc.w *= inv;
    *(float4*)(g_hmean + (size_t)node * DIM + lane * 4) = acc;
}

// ================= GEMM: C[M,128] = A[M,128] @ W[128,128] + bias =============

__global__ __launch_bounds__(256) void gemm_kernel(const float* __restrict__ A,
                                                   const float* __restrict__ W,
                                                   const float* __restrict__ bias,
                                                   float* __restrict__ C) {
    __shared__ float W_s[32][128];
    __shared__ float A_s[32][64];

    int t = threadIdx.x;
    int tx = t & 15;
    int ty = t >> 4;
    int row0 = blockIdx.x * 64;

    float acc[4][8];
#pragma unroll
    for (int i = 0; i < 4; i++)
#pragma unroll
        for (int j = 0; j < 8; j++) acc[i][j] = 0.0f;

    for (int k0 = 0; k0 < 128; k0 += 32) {
#pragma unroll
        for (int i = 0; i < 4; i++) {
            int f = i * 256 + t;
            int kk = f >> 5;
            int nq = f & 31;
            *(float4*)&W_s[kk][nq * 4] =
                *(const float4*)(W + (size_t)(k0 + kk) * 128 + nq * 4);
        }
#pragma unroll
        for (int i = 0; i < 2; i++) {
            int f = i * 256 + t;
            int row = f >> 3;
            int kq = f & 7;
            int grow = row0 + row;
            float4 v = make_float4(0.f, 0.f, 0.f, 0.f);
            if (grow < N_NODES)
                v = *(const float4*)(A + (size_t)grow * 128 + k0 + kq * 4);
            A_s[kq * 4 + 0][row] = v.x;
            A_s[kq * 4 + 1][row] = v.y;
            A_s[kq * 4 + 2][row] = v.z;
            A_s[kq * 4 + 3][row] = v.w;
        }
        __syncthreads();

#pragma unroll
        for (int kk = 0; kk < 32; kk++) {
            float4 a  = *(float4*)&A_s[kk][ty * 4];
            float4 w0 = *(float4*)&W_s[kk][tx * 8];
            float4 w1 = *(float4*)&W_s[kk][tx * 8 + 4];
            float av[4] = {a.x, a.y, a.z, a.w};
            float wv[8] = {w0.x, w0.y, w0.z, w0.w, w1.x, w1.y, w1.z, w1.w};
#pragma unroll
            for (int i = 0; i < 4; i++)
#pragma unroll
                for (int j = 0; j < 8; j++) acc[i][j] = fmaf(av[i], wv[j], acc[i][j]);
        }
        __syncthreads();
    }

    float4 b0 = *(const float4*)(bias + tx * 8);
    float4 b1 = *(const float4*)(bias + tx * 8 + 4);
#pragma unroll
    for (int i = 0; i < 4; i++) {
        int grow = row0 + ty * 4 + i;
        if (grow < N_NODES) {
            float4 o0 = make_float4(acc[i][0] + b0.x, acc[i][1] + b0.y,
                                    acc[i][2] + b0.z, acc[i][3] + b0.w);
            float4 o1 = make_float4(acc[i][4] + b1.x, acc[i][5] + b1.y,
                                    acc[i][6] + b1.z, acc[i][7] + b1.w);
            *(float4*)(C + (size_t)grow * 128 + tx * 8) = o0;
            *(float4*)(C + (size_t)grow * 128 + tx * 8 + 4) = o1;
        }
    }
}

__device__ __forceinline__ float leaky(float v) {
    return v > 0.0f ? v : NEG_SLOPE * v;
}

// ====== fused: edge score -> exp -> softmax-normalized weighted sum ==========
// out[d] = (sum_e sc_e * x[src_e]) / (sum_e sc_e)   — no atomics anywhere.
__global__ __launch_bounds__(256) void fused_attn_agg_kernel(
        const float* __restrict__ x,
        const float* __restrict__ att_w,
        const float* __restrict__ att_b,
        float* __restrict__ out) {
    int node = blockIdx.x * 8 + (threadIdx.x >> 5);
    if (node >= N_NODES) return;
    int lane = threadIdx.x & 31;
    int beg = g_row_ptr[node];
    int end = g_row_ptr[node + 1];

    if (beg == end) {   // no in-edges: segment sum is 0
        *(float4*)(out + (size_t)node * DIM + lane * 4) =
            make_float4(0.f, 0.f, 0.f, 0.f);
        return;
    }

    float4 b = *(const float4*)(g_ha_dst + (size_t)node * DIM + lane * 4);
    float4 w = *(const float4*)(att_w + lane * 4);
    float ab = att_b[0];

    float4 acc = make_float4(0.f, 0.f, 0.f, 0.f);
    float denom = 0.0f;

    for (int base = beg; base < end; base += 32) {
        int cnt = min(32, end - base);
        int s = (lane < cnt) ? g_csr_src[base + lane] : 0;
        for (int j = 0; j < cnt; j++) {
            int sj = __shfl_sync(0xFFFFFFFFu, s, j);
            float4 a = *(const float4*)(g_ha_src + (size_t)sj * DIM + lane * 4);
            float p = leaky(a.x + b.x) * w.x + leaky(a.y + b.y) * w.y +
                      leaky(a.z + b.z) * w.z + leaky(a.w + b.w) * w.w;
#pragma unroll
            for (int o = 16; o > 0; o >>= 1)
                p += __shfl_xor_sync(0xFFFFFFFFu, p, o);
            float sc = __expf(p + ab);
            float4 v = *(const float4*)(x + (size_t)sj * DIM + lane * 4);
            acc.x = fmaf(sc, v.x, acc.x);
            acc.y = fmaf(sc, v.y, acc.y);
            acc.z = fmaf(sc, v.z, acc.z);
            acc.w = fmaf(sc, v.w, acc.w);
            denom += sc;
        }
    }
    float inv = 1.0f / denom;
    acc.x *= inv; acc.y *= inv; acc.z *= inv; acc.w *= inv;
    *(float4*)(out + (size_t)node * DIM + lane * 4) = acc;
}

// ================= launcher =================

extern "C" void kernel_launch(void* const* d_in, const int* in_sizes, int n_in,
                              void* d_out, int out_size) {
    const float* x     = (const float*)d_in[0];
    const int*   src   = (const int*)d_in[1];
    const int*   dst   = (const int*)d_in[2];
    const float* src_w = (const float*)d_in[3];
    const float* src_b = (const float*)d_in[4];
    const float* dst_w = (const float*)d_in[5];
    const float* dst_b = (const float*)d_in[6];
    const float* att_w = (const float*)d_in[7];
    const float* att_b = (const float*)d_in[8];
    float* out = (float*)d_out;

    float *p_hmean, *p_ha_src, *p_ha_dst;
    cudaGetSymbolAddress((void**)&p_hmean,  g_hmean);
    cudaGetSymbolAddress((void**)&p_ha_src, g_ha_src);
    cudaGetSymbolAddress((void**)&p_ha_dst, g_ha_dst);

    const int NODE_WARP_BLOCKS = (N_NODES + 7) / 8;
    const int GEMM_BLOCKS = (N_NODES + 63) / 64;

    zero_count_kernel<<<(N_NODES + 255) / 256, 256>>>();
    count_kernel<<<(N_EDGES + 255) / 256, 256>>>(dst);
    scan_kernel<<<1, 1024>>>();
    fill_kernel<<<(N_EDGES + 255) / 256, 256>>>(src, dst);
    mean_kernel<<<NODE_WARP_BLOCKS, 256>>>(x);
    gemm_kernel<<<GEMM_BLOCKS, 256>>>(x,       src_w, src_b, p_ha_src);
    gemm_kernel<<<GEMM_BLOCKS, 256>>>(p_hmean, dst_w, dst_b, p_ha_dst);
    fused_attn_agg_kernel<<<NODE_WARP_BLOCKS, 256>>>(x, att_w, att_b, out);
}

// round 9
// speedup vs baseline: 3.5227x; 1.5674x over previous
#include <cuda_runtime.h>

#define N_NODES 50000
#define N_EDGES 800000
#define DIM 128
#define NEG_SLOPE 0.01f
#define NB_SCAN ((N_NODES + 255) / 256)

typedef unsigned long long u64;

// -------- scratch (allocation-free rule: __device__ globals) --------
__device__ int   g_count[N_NODES];          // degree counts / fill cursors
__device__ int   g_row_ptr[N_NODES + 1];    // CSR row pointers (by dst)
__device__ int   g_bsum[NB_SCAN];           // scan partials
__device__ int   g_csr_src[N_EDGES];        // src index per CSR slot
__device__ float g_y[(size_t)N_NODES * DIM];       // y = x @ dst_w
__device__ float g_ha_src[(size_t)N_NODES * DIM];
__device__ float g_ha_dst[(size_t)N_NODES * DIM];

// ================= CSR build =================

__global__ void count_kernel(const int* __restrict__ dst) {
    int e = blockIdx.x * blockDim.x + threadIdx.x;
    if (e < N_EDGES) atomicAdd(&g_count[dst[e]], 1);
}

// block-level exclusive scan; writes per-element exclusive prefix and block sum.
__global__ __launch_bounds__(256) void scan1_kernel() {
    __shared__ int wsum[8];
    int tid = threadIdx.x, b = blockIdx.x;
    int i = b * 256 + tid;
    int v = (i < N_NODES) ? g_count[i] : 0;
    if (i < N_NODES) g_count[i] = 0;        // reset cursors for fill
    int lane = tid & 31, wid = tid >> 5;
    int incl = v;
#pragma unroll
    for (int o = 1; o < 32; o <<= 1) {
        int t = __shfl_up_sync(0xFFFFFFFFu, incl, o);
        if (lane >= o) incl += t;
    }
    if (lane == 31) wsum[wid] = incl;
    __syncthreads();
    if (tid < 32) {
        int s = (tid < 8) ? wsum[tid] : 0;
        int inc = s;
#pragma unroll
        for (int o = 1; o < 8; o <<= 1) {
            int t = __shfl_up_sync(0xFFFFFFFFu, inc, o);
            if (tid >= o) inc += t;
        }
        if (tid < 8) wsum[tid] = inc - s;   // exclusive warp offsets
    }
    __syncthreads();
    int excl = (incl - v) + wsum[wid];
    if (i < N_NODES) g_row_ptr[i] = excl;
    if (tid == 255) g_bsum[b] = excl + v;   // block total
}

// single-block exclusive scan of the NB_SCAN block sums.
__global__ __launch_bounds__(256) void scan2_kernel() {
    __shared__ int wsum[8];
    int tid = threadIdx.x;
    int v = (tid < NB_SCAN) ? g_bsum[tid] : 0;
    int lane = tid & 31, wid = tid >> 5;
    int incl = v;
#pragma unroll
    for (int o = 1; o < 32; o <<= 1) {
        int t = __shfl_up_sync(0xFFFFFFFFu, incl, o);
        if (lane >= o) incl += t;
    }
    if (lane == 31) wsum[wid] = incl;
    __syncthreads();
    if (tid < 32) {
        int s = (tid < 8) ? wsum[tid] : 0;
        int inc = s;
#pragma unroll
        for (int o = 1; o < 8; o <<= 1) {
            int t = __shfl_up_sync(0xFFFFFFFFu, inc, o);
            if (tid >= o) inc += t;
        }
        if (tid < 8) wsum[tid] = inc - s;
    }
    __syncthreads();
    int excl = (incl - v) + wsum[wid];
    if (tid < NB_SCAN) g_bsum[tid] = excl;
    if (tid == 255) g_row_ptr[N_NODES] = excl + v;  // grand total = N_EDGES
}

__global__ void scan3_kernel() {
    int i = blockIdx.x * 256 + threadIdx.x;
    if (i < N_NODES) g_row_ptr[i] += g_bsum[blockIdx.x];
}

__global__ void fill_kernel(const int* __restrict__ src,
                            const int* __restrict__ dst) {
    int e = blockIdx.x * blockDim.x + threadIdx.x;
    if (e < N_EDGES) {
        int d = dst[e];
        int pos = g_row_ptr[d] + atomicAdd(&g_count[d], 1);
        g_csr_src[pos] = src[e];
    }
}

// ====== mean aggregation of y rows: ha_dst = mean(y[src])[node] + dst_b ======

__global__ __launch_bounds__(256) void mean_kernel(const float* __restrict__ bias) {
    int node = blockIdx.x * 8 + (threadIdx.x >> 5);
    if (node >= N_NODES) return;
    int lane = threadIdx.x & 31;
    int beg = g_row_ptr[node];
    int end = g_row_ptr[node + 1];

    float4 acc = make_float4(0.f, 0.f, 0.f, 0.f);
    for (int base = beg; base < end; base += 32) {
        int cnt = min(32, end - base);
        int s = (lane < cnt) ? g_csr_src[base + lane] : 0;
#pragma unroll 4
        for (int j = 0; j < cnt; j++) {
            int sj = __shfl_sync(0xFFFFFFFFu, s, j);
            float4 v = *(const float4*)(g_y + (size_t)sj * DIM + lane * 4);
            acc.x += v.x; acc.y += v.y; acc.z += v.z; acc.w += v.w;
        }
    }
    float inv = 1.0f / fmaxf((float)(end - beg), 1.0f);
    float4 b = *(const float4*)(bias + lane * 4);
    acc.x = acc.x * inv + b.x;
    acc.y = acc.y * inv + b.y;
    acc.z = acc.z * inv + b.z;
    acc.w = acc.w * inv + b.w;
    *(float4*)(g_ha_dst + (size_t)node * DIM + lane * 4) = acc;
}

// ================= GEMM: C[M,128] = A[M,128] @ W[128,128] (+bias) ============
// 128x128 block tile, 8x8 micro-tile, packed fp32x2 FMA (FFMA2).
// Thread tx owns column PAIRS {2tx, 2tx+32, 2tx+64, 2tx+96} (conflict-free LDS.64).

__device__ __forceinline__ u64 pack_dup(float v) {
    u64 d; unsigned r = __float_as_uint(v);
    asm("mov.b64 %0, {%1, %1};" : "=l"(d) : "r"(r));
    return d;
}
__device__ __forceinline__ u64 ffma2(u64 a, u64 b, u64 c) {
    u64 d;
    asm("fma.rn.f32x2 %0, %1, %2, %3;" : "=l"(d) : "l"(a), "l"(b), "l"(c));
    return d;
}

__global__ __launch_bounds__(256) void gemm_kernel(const float* __restrict__ A,
                                                   const float* __restrict__ W,
                                                   const float* __restrict__ bias,
                                                   float* __restrict__ C) {
    __shared__ __align__(16) float A_s[16][132];   // [k][row], padded
    __shared__ __align__(16) float W_s[16][128];   // [k][col]

    int t = threadIdx.x;
    int tx = t & 15;
    int ty = t >> 4;
    int row0 = blockIdx.x * 128;

    u64 acc[8][4];
#pragma unroll
    for (int i = 0; i < 8; i++)
#pragma unroll
        for (int j = 0; j < 4; j++) acc[i][j] = 0ull;

    for (int k0 = 0; k0 < 128; k0 += 16) {
        // W chunk: 16x128 floats = 512 float4, 2 per thread
#pragma unroll
        for (int i = 0; i < 2; i++) {
            int idx = i * 256 + t;
            int kk = idx >> 5, q = idx & 31;
            *(float4*)&W_s[kk][q * 4] =
                *(const float4*)(W + (k0 + kk) * 128 + q * 4);
        }
        // A chunk: 128 rows x 16 k = 512 float4, 2 per thread, transposed store
#pragma unroll
        for (int i = 0; i < 2; i++) {
            int idx = i * 256 + t;
            int row = idx >> 2, q = idx & 3;
            int gr = row0 + row;
            float4 v = make_float4(0.f, 0.f, 0.f, 0.f);
            if (gr < N_NODES)
                v = *(const float4*)(A + (size_t)gr * 128 + k0 + q * 4);
            A_s[q * 4 + 0][row] = v.x;
            A_s[q * 4 + 1][row] = v.y;
            A_s[q * 4 + 2][row] = v.z;
            A_s[q * 4 + 3][row] = v.w;
        }
        __syncthreads();

#pragma unroll
        for (int kk = 0; kk < 16; kk++) {
            float4 a0 = *(float4*)&A_s[kk][ty * 8];
            float4 a1 = *(float4*)&A_s[kk][ty * 8 + 4];
            u64 w2[4];
#pragma unroll
            for (int j = 0; j < 4; j++)
                w2[j] = *(const u64*)&W_s[kk][2 * tx + 32 * j];
            float av[8] = {a0.x, a0.y, a0.z, a0.w, a1.x, a1.y, a1.z, a1.w};
#pragma unroll
            for (int i = 0; i < 8; i++) {
                u64 ad = pack_dup(av[i]);
#pragma unroll
                for (int j = 0; j < 4; j++)
                    acc[i][j] = ffma2(ad, w2[j], acc[i][j]);
            }
        }
        __syncthreads();
    }

    float2 bv[4];
#pragma unroll
    for (int j = 0; j < 4; j++)
        bv[j] = bias ? *(const float2*)(bias + 2 * tx + 32 * j)
                     : make_float2(0.f, 0.f);
#pragma unroll
    for (int i = 0; i < 8; i++) {
        int gr = row0 + ty * 8 + i;
        if (gr < N_NODES) {
            float* cp = C + (size_t)gr * 128;
#pragma unroll
            for (int j = 0; j < 4; j++) {
                float2 v = *(float2*)&acc[i][j];
                v.x += bv[j].x; v.y += bv[j].y;
                *(float2*)(cp + 2 * tx + 32 * j) = v;
            }
        }
    }
}

__device__ __forceinline__ float leaky(float v) {
    return v > 0.0f ? v : NEG_SLOPE * v;
}

// ====== fused: edge score -> exp -> softmax-normalized weighted sum ==========
__global__ __launch_bounds__(256) void fused_attn_agg_kernel(
        const float* __restrict__ x,
        const float* __restrict__ att_w,
        const float* __restrict__ att_b,
        float* __restrict__ out) {
    int node = blockIdx.x * 8 + (threadIdx.x >> 5);
    if (node >= N_NODES) return;
    int lane = threadIdx.x & 31;
    int beg = g_row_ptr[node];
    int end = g_row_ptr[node + 1];

    if (beg == end) {
        *(float4*)(out + (size_t)node * DIM + lane * 4) =
            make_float4(0.f, 0.f, 0.f, 0.f);
        return;
    }

    float4 b = *(const float4*)(g_ha_dst + (size_t)node * DIM + lane * 4);
    float4 w = *(const float4*)(att_w + lane * 4);
    float ab = att_b[0];

    float4 acc = make_float4(0.f, 0.f, 0.f, 0.f);
    float denom = 0.0f;

    for (int base = beg; base < end; base += 32) {
        int cnt = min(32, end - base);
        int s = (lane < cnt) ? g_csr_src[base + lane] : 0;
        for (int j = 0; j < cnt; j++) {
            int sj = __shfl_sync(0xFFFFFFFFu, s, j);
            float4 a = *(const float4*)(g_ha_src + (size_t)sj * DIM + lane * 4);
            float p = leaky(a.x + b.x) * w.x + leaky(a.y + b.y) * w.y +
                      leaky(a.z + b.z) * w.z + leaky(a.w + b.w) * w.w;
#pragma unroll
            for (int o = 16; o > 0; o >>= 1)
                p += __shfl_xor_sync(0xFFFFFFFFu, p, o);
            float sc = __expf(p + ab);
            float4 v = *(const float4*)(x + (size_t)sj * DIM + lane * 4);
            acc.x = fmaf(sc, v.x, acc.x);
            acc.y = fmaf(sc, v.y, acc.y);
            acc.z = fmaf(sc, v.z, acc.z);
            acc.w = fmaf(sc, v.w, acc.w);
            denom += sc;
        }
    }
    float inv = 1.0f / denom;
    acc.x *= inv; acc.y *= inv; acc.z *= inv; acc.w *= inv;
    *(float4*)(out + (size_t)node * DIM + lane * 4) = acc;
}

// ================= launcher (fork/join inside graph capture) =================

extern "C" void kernel_launch(void* const* d_in, const int* in_sizes, int n_in,
                              void* d_out, int out_size) {
    const float* x     = (const float*)d_in[0];
    const int*   src   = (const int*)d_in[1];
    const int*   dst   = (const int*)d_in[2];
    const float* src_w = (const float*)d_in[3];
    const float* src_b = (const float*)d_in[4];
    const float* dst_w = (const float*)d_in[5];
    const float* dst_b = (const float*)d_in[6];
    const float* att_w = (const float*)d_in[7];
    const float* att_b = (const float*)d_in[8];
    float* out = (float*)d_out;

    float *p_y, *p_ha_src;
    int   *p_count;
    cudaGetSymbolAddress((void**)&p_y,      g_y);
    cudaGetSymbolAddress((void**)&p_ha_src, g_ha_src);
    cudaGetSymbolAddress((void**)&p_count,  g_count);

    const int NODE_WARP_BLOCKS = (N_NODES + 7) / 8;     // 6250
    const int GEMM_BLOCKS = (N_NODES + 127) / 128;      // 391

    // side stream + events for fork/join (created per call; NOT destroyed —
    // destroying a capture-participating stream would invalidate the capture;
    // kernel_launch is only invoked a handful of times, never in the timed loop)
    cudaStream_t s1;
    cudaStreamCreateWithFlags(&s1, cudaStreamNonBlocking);
    cudaEvent_t evFork, evY, evSrc;
    cudaEventCreateWithFlags(&evFork, cudaEventDisableTiming);
    cudaEventCreateWithFlags(&evY,    cudaEventDisableTiming);
    cudaEventCreateWithFlags(&evSrc,  cudaEventDisableTiming);

    // fork: GEMMs on side stream
    cudaEventRecord(evFork, 0);
    cudaStreamWaitEvent(s1, evFork, 0);
    gemm_kernel<<<GEMM_BLOCKS, 256, 0, s1>>>(x, dst_w, nullptr, p_y);
    cudaEventRecord(evY, s1);
    gemm_kernel<<<GEMM_BLOCKS, 256, 0, s1>>>(x, src_w, src_b, p_ha_src);
    cudaEventRecord(evSrc, s1);

    // main stream: CSR build
    cudaMemsetAsync(p_count, 0, N_NODES * sizeof(int), 0);
    count_kernel<<<(N_EDGES + 255) / 256, 256>>>(dst);
    scan1_kernel<<<NB_SCAN, 256>>>();
    scan2_kernel<<<1, 256>>>();
    scan3_kernel<<<NB_SCAN, 256>>>();
    fill_kernel<<<(N_EDGES + 255) / 256, 256>>>(src, dst);

    // join y -> mean aggregation of y
    cudaStreamWaitEvent(0, evY, 0);
    mean_kernel<<<NODE_WARP_BLOCKS, 256>>>(dst_b);

    // join ha_src -> fused attention + aggregation
    cudaStreamWaitEvent(0, evSrc, 0);
    fused_attn_agg_kernel<<<NODE_WARP_BLOCKS, 256>>>(x, att_w, att_b, out);
}